// round 1
// baseline (speedup 1.0000x reference)
#include <cuda_runtime.h>
#include <math.h>

#define BATCH 4
#define SEQ   512
#define HD    768
#define DD    24
#define MMDIM 96
#define OO    768
#define ROWS  (BATCH*SEQ)       // 2048
#define XCOLS (3*HD)            // 2304

// ---------------- scratch (no allocations allowed) ----------------
__device__ float g_Zj[ROWS*DD];
__device__ float g_Zi[ROWS*DD];
__device__ float g_tjb[ROWS*MMDIM];
__device__ float g_ti[ROWS*MMDIM];
__device__ float g_probs[(long)BATCH*SEQ*SEQ];
__device__ float g_ctx[(long)ROWS*HD];
__device__ float g_X[(long)ROWS*XCOLS];
__device__ float g_mhid[(long)ROWS*OO];

// ---------------- generic register-tiled SGEMM ----------------
// C[M,N] = epilogue(A[M,K] @ B[K,N]); A,B,C row-major. Optional batch via gridDim.z.
template<bool BIAS, bool RELU, bool SCALE>
__global__ __launch_bounds__(256)
void sgemm_kernel(const float* __restrict__ A, const float* __restrict__ B,
                  float* __restrict__ C,
                  int M, int N, int K, int lda, int ldb, int ldc,
                  const float* __restrict__ bias,
                  const float* __restrict__ alpha_ptr,
                  long sA, long sB, long sC)
{
    __shared__ float As[16][64];   // As[k][row]
    __shared__ float Bs[16][64];   // Bs[k][col]

    const int bz = blockIdx.z;
    A += (long)bz * sA;  B += (long)bz * sB;  C += (long)bz * sC;

    const int tid = threadIdx.x;
    const int tx = tid & 15, ty = tid >> 4;
    const int row0 = blockIdx.y * 64;
    const int col0 = blockIdx.x * 64;

    float acc[4][4] = {};

    for (int k0 = 0; k0 < K; k0 += 16) {
        #pragma unroll
        for (int u = 0; u < 4; ++u) {                 // A tile 64x16
            int t = tid + u * 256;
            int r = t >> 4, kk = t & 15;
            int gr = row0 + r, gk = k0 + kk;
            float v = 0.f;
            if (gr < M && gk < K) v = A[(long)gr * lda + gk];
            As[kk][r] = v;
        }
        #pragma unroll
        for (int u = 0; u < 4; ++u) {                 // B tile 16x64
            int t = tid + u * 256;
            int kk = t >> 6, n = t & 63;
            int gk = k0 + kk, gn = col0 + n;
            float v = 0.f;
            if (gk < K && gn < N) v = B[(long)gk * ldb + gn];
            Bs[kk][n] = v;
        }
        __syncthreads();
        #pragma unroll
        for (int kk = 0; kk < 16; ++kk) {
            float4 a4 = *(const float4*)&As[kk][ty * 4];
            float4 b4 = *(const float4*)&Bs[kk][tx * 4];
            float a[4] = {a4.x, a4.y, a4.z, a4.w};
            float b[4] = {b4.x, b4.y, b4.z, b4.w};
            #pragma unroll
            for (int i = 0; i < 4; ++i)
                #pragma unroll
                for (int j = 0; j < 4; ++j)
                    acc[i][j] = fmaf(a[i], b[j], acc[i][j]);
        }
        __syncthreads();
    }

    float alpha = 1.f;
    if (SCALE) alpha = *alpha_ptr;

    #pragma unroll
    for (int i = 0; i < 4; ++i) {
        int r = row0 + ty * 4 + i;
        if (r >= M) continue;
        #pragma unroll
        for (int j = 0; j < 4; ++j) {
            int c = col0 + tx * 4 + j;
            if (c >= N) continue;
            float v = acc[i][j];
            if (BIAS) v += bias[c];
            if (RELU) v = fmaxf(v, 0.f);
            C[(long)r * ldc + c] = alpha * v;
        }
    }
}

// ---------------- fused pairwise logits + softmax ----------------
// One block per (b,p). For each q: hid_m = relu(tjb[p,m] + ti[q,m] + g(p,q) @ Wcat[:,m]),
// logit = hid . ws2 + bs2; then mask + softmax over q; write probs row.
// g(p,q)[d<24]  = Zj[p,d]*Zi[q,d]            (W1h rows = Ws1[48+d])
// g(p,q)[d>=24] = |Zj[p,d-24]-Zi[q,d-24]|    (W1d rows = Ws1[48+d])
__global__ __launch_bounds__(256)
void pairwise_kernel(const float* __restrict__ Zj, const float* __restrict__ Zi,
                     const float* __restrict__ tjb, const float* __restrict__ ti,
                     const float* __restrict__ Ws1, const float* __restrict__ ws2,
                     const float* __restrict__ bs2, const int* __restrict__ attn_mask,
                     float* __restrict__ probs)
{
    __shared__ float Wc_s[48][96];     // Ws1 rows 48..95
    __shared__ float Gs[48][64];       // g vectors for 64 q, k-major
    __shared__ float Zis[64][24];
    __shared__ float Zjp_s[24];
    __shared__ float tjb_s[96];
    __shared__ float ws2_s[96];
    __shared__ float logits_s[512];
    __shared__ float red_s[256];

    const int tid = threadIdx.x;
    const int tx = tid & 15, ty = tid >> 4;
    const int pg = blockIdx.x;                 // 0..2047
    const int b = pg >> 9;

    for (int idx = tid; idx < 48 * 96; idx += 256)
        (&Wc_s[0][0])[idx] = Ws1[48 * 96 + idx];
    if (tid < 24) Zjp_s[tid] = Zj[pg * 24 + tid];
    if (tid < 96) { tjb_s[tid] = tjb[pg * 96 + tid]; ws2_s[tid] = ws2[tid]; }
    __syncthreads();

    for (int qt = 0; qt < 8; ++qt) {
        const int q0 = qt * 64;
        for (int idx = tid; idx < 64 * 24; idx += 256) {
            int q = idx / 24, d = idx % 24;
            Zis[q][d] = Zi[(b * 512 + q0 + q) * 24 + d];
        }
        __syncthreads();
        for (int idx = tid; idx < 48 * 64; idx += 256) {
            int k = idx >> 6, q = idx & 63;
            float v;
            if (k < 24) v = Zjp_s[k] * Zis[q][k];
            else        v = fabsf(Zjp_s[k - 24] - Zis[q][k - 24]);
            Gs[k][q] = v;
        }
        __syncthreads();

        // register-tiled (64q x 96m) = G(64x48) @ Wcat(48x96); thread: 4q x 6m
        float acc[4][6] = {};
        #pragma unroll
        for (int k = 0; k < 48; ++k) {
            float4 gg  = *(const float4*)&Gs[k][ty * 4];
            float2 w01 = *(const float2*)&Wc_s[k][tx * 6];
            float2 w23 = *(const float2*)&Wc_s[k][tx * 6 + 2];
            float2 w45 = *(const float2*)&Wc_s[k][tx * 6 + 4];
            float g[4] = {gg.x, gg.y, gg.z, gg.w};
            float w[6] = {w01.x, w01.y, w23.x, w23.y, w45.x, w45.y};
            #pragma unroll
            for (int i = 0; i < 4; ++i)
                #pragma unroll
                for (int j = 0; j < 6; ++j)
                    acc[i][j] = fmaf(g[i], w[j], acc[i][j]);
        }

        // epilogue: + tjb + ti, relu, dot ws2, reduce over the 16 tx lanes
        const int qrow0 = b * 512 + q0;
        #pragma unroll
        for (int i = 0; i < 4; ++i) {
            int q = ty * 4 + i;
            const float* tirow = &ti[(long)(qrow0 + q) * 96];
            float s = 0.f;
            #pragma unroll
            for (int j = 0; j < 6; ++j) {
                int m = tx * 6 + j;
                float h = acc[i][j] + tjb_s[m] + tirow[m];
                h = fmaxf(h, 0.f);
                s = fmaf(h, ws2_s[m], s);
            }
            s += __shfl_xor_sync(0xffffffffu, s, 1);
            s += __shfl_xor_sync(0xffffffffu, s, 2);
            s += __shfl_xor_sync(0xffffffffu, s, 4);
            s += __shfl_xor_sync(0xffffffffu, s, 8);
            if (tx == 0) logits_s[q0 + q] = s;
        }
        __syncthreads();
    }

    // mask + bs2
    const float bs2v = *bs2;
    for (int q = tid; q < 512; q += 256) {
        float mv = (float)attn_mask[b * 512 + q];
        logits_s[q] += bs2v + (1.f - mv) * (-3.402823466e38f);
    }
    __syncthreads();

    // softmax over 512
    float lmax = -INFINITY;
    for (int q = tid; q < 512; q += 256) lmax = fmaxf(lmax, logits_s[q]);
    red_s[tid] = lmax; __syncthreads();
    for (int s = 128; s > 0; s >>= 1) {
        if (tid < s) red_s[tid] = fmaxf(red_s[tid], red_s[tid + s]);
        __syncthreads();
    }
    lmax = red_s[0];
    __syncthreads();

    float lsum = 0.f;
    for (int q = tid; q < 512; q += 256) {
        float e = expf(logits_s[q] - lmax);
        logits_s[q] = e;
        lsum += e;
    }
    red_s[tid] = lsum; __syncthreads();
    for (int s = 128; s > 0; s >>= 1) {
        if (tid < s) red_s[tid] += red_s[tid + s];
        __syncthreads();
    }
    const float inv = 1.f / red_s[0];
    for (int q = tid; q < 512; q += 256)
        probs[(long)pg * 512 + q] = logits_s[q] * inv;
}

// ---------------- X = [ctx | H_j | ctx*H_j] ----------------
__global__ void buildX_kernel(const float* __restrict__ ctx,
                              const float* __restrict__ Hj,
                              float* __restrict__ X)
{
    long i = (long)blockIdx.x * 256 + threadIdx.x;
    if (i >= (long)ROWS * XCOLS) return;
    int r = (int)(i / XCOLS);
    int c = (int)(i % XCOLS);
    float v;
    if (c < HD)            v = ctx[(long)r * HD + c];
    else if (c < 2 * HD)   v = Hj[(long)r * HD + (c - HD)];
    else                   v = ctx[(long)r * HD + (c - 2 * HD)] * Hj[(long)r * HD + (c - 2 * HD)];
    X[i] = v;
}

// ---------------- launch ----------------
extern "C" void kernel_launch(void* const* d_in, const int* in_sizes, int n_in,
                              void* d_out, int out_size)
{
    const float* Hj   = (const float*)d_in[0];
    const float* Hi   = (const float*)d_in[1];
    const float* Wpj  = (const float*)d_in[2];
    const float* Wpi  = (const float*)d_in[3];
    const float* Ws1  = (const float*)d_in[4];
    const float* bs1  = (const float*)d_in[5];
    const float* ws2  = (const float*)d_in[6];
    const float* bs2  = (const float*)d_in[7];
    const float* Wv1  = (const float*)d_in[8];
    const float* bv1  = (const float*)d_in[9];
    const float* Wv2  = (const float*)d_in[10];
    const float* bv2  = (const float*)d_in[11];
    const float* alpha= (const float*)d_in[12];
    const int*   mask = (const int*)d_in[13];
    float* out = (float*)d_out;

    float *Zj, *Zi, *tjb, *ti, *probs, *ctx, *X, *mhid;
    cudaGetSymbolAddress((void**)&Zj, g_Zj);
    cudaGetSymbolAddress((void**)&Zi, g_Zi);
    cudaGetSymbolAddress((void**)&tjb, g_tjb);
    cudaGetSymbolAddress((void**)&ti, g_ti);
    cudaGetSymbolAddress((void**)&probs, g_probs);
    cudaGetSymbolAddress((void**)&ctx, g_ctx);
    cudaGetSymbolAddress((void**)&X, g_X);
    cudaGetSymbolAddress((void**)&mhid, g_mhid);

    // Zj = H_j @ Wpj ; Zi = H_i @ Wpi          (2048 x 24, K=768)
    sgemm_kernel<false,false,false><<<dim3(1, ROWS/64, 1), 256>>>(
        Hj, Wpj, Zj, ROWS, DD, HD, HD, DD, DD, nullptr, nullptr, 0, 0, 0);
    sgemm_kernel<false,false,false><<<dim3(1, ROWS/64, 1), 256>>>(
        Hi, Wpi, Zi, ROWS, DD, HD, HD, DD, DD, nullptr, nullptr, 0, 0, 0);

    // tjb = Zj @ Ws1[0:24] + bs1 ; ti = Zi @ Ws1[24:48]     (2048 x 96, K=24)
    sgemm_kernel<true,false,false><<<dim3(2, ROWS/64, 1), 256>>>(
        Zj, Ws1, tjb, ROWS, MMDIM, DD, DD, MMDIM, MMDIM, bs1, nullptr, 0, 0, 0);
    sgemm_kernel<false,false,false><<<dim3(2, ROWS/64, 1), 256>>>(
        Zi, Ws1 + DD * MMDIM, ti, ROWS, MMDIM, DD, DD, MMDIM, MMDIM, nullptr, nullptr, 0, 0, 0);

    // fused pairwise logits + softmax -> probs
    pairwise_kernel<<<ROWS, 256>>>(Zj, Zi, tjb, ti, Ws1, ws2, bs2, mask, probs);

    // ctx = probs @ H_i   (batched 4x: 512 x 768, K=512)
    sgemm_kernel<false,false,false><<<dim3(HD/64, SEQ/64, BATCH), 256>>>(
        probs, Hi, ctx, SEQ, HD, SEQ, SEQ, HD, HD, nullptr, nullptr,
        (long)SEQ*SEQ, (long)SEQ*HD, (long)SEQ*HD);

    // X = [ctx | H_j | ctx*H_j]
    buildX_kernel<<<(int)(((long)ROWS*XCOLS + 255) / 256), 256>>>(ctx, Hj, X);

    // mhid = relu(X @ Wv1 + bv1)   (2048 x 768, K=2304)
    sgemm_kernel<true,true,false><<<dim3(OO/64, ROWS/64, 1), 256>>>(
        X, Wv1, mhid, ROWS, OO, XCOLS, XCOLS, OO, OO, bv1, nullptr, 0, 0, 0);

    // out = alpha * (mhid @ Wv2 + bv2)   (2048 x 768, K=768)
    sgemm_kernel<true,false,true><<<dim3(HD/64, ROWS/64, 1), 256>>>(
        mhid, Wv2, out, ROWS, HD, OO, OO, HD, HD, bv2, alpha, 0, 0, 0);
}

// round 2
// speedup vs baseline: 1.1737x; 1.1737x over previous
#include <cuda_runtime.h>
#include <math.h>

#define BATCH 4
#define SEQ   512
#define HD    768
#define DD    24
#define MMDIM 96
#define OO    768
#define ROWS  (BATCH*SEQ)       // 2048
#define XCOLS (3*HD)            // 2304

typedef unsigned long long ull;

// ---------------- scratch (no allocations allowed) ----------------
__device__ float g_Zj[ROWS*DD];
__device__ float g_Zi[ROWS*DD];
__device__ float g_tjb[ROWS*MMDIM];
__device__ float g_ti[ROWS*MMDIM];
__device__ float g_probs[(long)BATCH*SEQ*SEQ];
__device__ float g_ctx[(long)ROWS*HD];
__device__ float g_mhid[(long)ROWS*OO];

// ---------------- packed f32x2 helpers ----------------
__device__ __forceinline__ ull pk2(float x) {
    ull r; asm("mov.b64 %0, {%1, %1};" : "=l"(r) : "f"(x)); return r;
}
__device__ __forceinline__ void fma2(ull &d, ull a, ull b) {
    asm("fma.rn.f32x2 %0, %1, %2, %0;" : "+l"(d) : "l"(a), "l"(b));
}
__device__ __forceinline__ float2 up2(ull v) {
    float2 r; asm("mov.b64 {%0, %1}, %2;" : "=f"(r.x), "=f"(r.y) : "l"(v)); return r;
}

// ---------------- small generic SGEMM (projections; guarded) ----------------
template<bool BIAS>
__global__ __launch_bounds__(256)
void sgemm_small(const float* __restrict__ A, const float* __restrict__ B,
                 float* __restrict__ C,
                 int M, int N, int K, int lda, int ldb, int ldc,
                 const float* __restrict__ bias)
{
    __shared__ float As[16][64];
    __shared__ float Bs[16][64];
    const int tid = threadIdx.x;
    const int tx = tid & 15, ty = tid >> 4;
    const int row0 = blockIdx.y * 64;
    const int col0 = blockIdx.x * 64;

    float acc[4][4] = {};
    for (int k0 = 0; k0 < K; k0 += 16) {
        #pragma unroll
        for (int u = 0; u < 4; ++u) {
            int t = tid + u * 256;
            int r = t >> 4, kk = t & 15;
            int gr = row0 + r, gk = k0 + kk;
            float v = 0.f;
            if (gr < M && gk < K) v = A[(long)gr * lda + gk];
            As[kk][r] = v;
        }
        #pragma unroll
        for (int u = 0; u < 4; ++u) {
            int t = tid + u * 256;
            int kk = t >> 6, n = t & 63;
            int gk = k0 + kk, gn = col0 + n;
            float v = 0.f;
            if (gk < K && gn < N) v = B[(long)gk * ldb + gn];
            Bs[kk][n] = v;
        }
        __syncthreads();
        #pragma unroll
        for (int kk = 0; kk < 16; ++kk) {
            float4 a4 = *(const float4*)&As[kk][ty * 4];
            float4 b4 = *(const float4*)&Bs[kk][tx * 4];
            float a[4] = {a4.x, a4.y, a4.z, a4.w};
            float b[4] = {b4.x, b4.y, b4.z, b4.w};
            #pragma unroll
            for (int i = 0; i < 4; ++i)
                #pragma unroll
                for (int j = 0; j < 4; ++j)
                    acc[i][j] = fmaf(a[i], b[j], acc[i][j]);
        }
        __syncthreads();
    }
    #pragma unroll
    for (int i = 0; i < 4; ++i) {
        int r = row0 + ty * 4 + i;
        if (r >= M) continue;
        #pragma unroll
        for (int j = 0; j < 4; ++j) {
            int c = col0 + tx * 4 + j;
            if (c >= N) continue;
            float v = acc[i][j];
            if (BIAS) v += bias[c];
            C[(long)r * ldc + c] = v;
        }
    }
}

// ---------------- 64x64 FFMA2 GEMM (exact-multiple dims, unguarded) ----------------
// 64 threads, microtile 8x8 (rows ty*4+{0..3,32..35}, cols tx*4+{0..3,32..35}).
// AMODE 0: A pointer. AMODE 1: A = [ctx | Hj | ctx*Hj] generated on the fly (lda=768 regions).
template<int AMODE, bool BIAS, bool RELU, bool SCALE>
__global__ __launch_bounds__(64)
void gemm64(const float* __restrict__ A, const float* __restrict__ B,
            float* __restrict__ C, int K, int lda, int ldb, int ldc,
            const float* __restrict__ bias, const float* __restrict__ alpha_ptr,
            long sA, long sB, long sC,
            const float* __restrict__ Actx, const float* __restrict__ Ahj)
{
    __shared__ float As[16][68];
    __shared__ float Bs[16][68];

    const int bz = blockIdx.z;
    if (AMODE == 0) A += (long)bz * sA;
    B += (long)bz * sB;  C += (long)bz * sC;

    const int tid = threadIdx.x;
    const int tx = tid & 7, ty = tid >> 3;
    const int row0 = blockIdx.y * 64;
    const int col0 = blockIdx.x * 64;

    ull acc[8][4];
    #pragma unroll
    for (int i = 0; i < 8; ++i)
        #pragma unroll
        for (int j = 0; j < 4; ++j) acc[i][j] = 0ull;

    for (int k0 = 0; k0 < K; k0 += 16) {
        // ---- load A tile (64r x 16k), transpose into As[k][r] ----
        #pragma unroll
        for (int u = 0; u < 4; ++u) {
            int lin = tid + u * 64;
            int r = lin >> 2, kc = lin & 3;
            float4 v;
            if (AMODE == 0) {
                v = *(const float4*)&A[(long)(row0 + r) * lda + k0 + kc * 4];
            } else {
                int gk = k0 + kc * 4;
                long ridx = (long)(row0 + r) * HD;
                if (gk < HD) {
                    v = *(const float4*)&Actx[ridx + gk];
                } else if (gk < 2 * HD) {
                    v = *(const float4*)&Ahj[ridx + gk - HD];
                } else {
                    float4 c4 = *(const float4*)&Actx[ridx + gk - 2 * HD];
                    float4 h4 = *(const float4*)&Ahj[ridx + gk - 2 * HD];
                    v.x = c4.x * h4.x; v.y = c4.y * h4.y;
                    v.z = c4.z * h4.z; v.w = c4.w * h4.w;
                }
            }
            As[kc * 4 + 0][r] = v.x;
            As[kc * 4 + 1][r] = v.y;
            As[kc * 4 + 2][r] = v.z;
            As[kc * 4 + 3][r] = v.w;
        }
        // ---- load B tile (16k x 64n) ----
        #pragma unroll
        for (int u = 0; u < 4; ++u) {
            int lin = tid + u * 64;
            int kk = lin >> 4, n4 = lin & 15;
            float4 v = *(const float4*)&B[(long)(k0 + kk) * ldb + col0 + n4 * 4];
            *(float4*)&Bs[kk][n4 * 4] = v;
        }
        __syncthreads();

        #pragma unroll
        for (int kk = 0; kk < 16; ++kk) {
            float4 a0 = *(const float4*)&As[kk][ty * 4];
            float4 a1 = *(const float4*)&As[kk][ty * 4 + 32];
            ulonglong2 bl = *(const ulonglong2*)&Bs[kk][tx * 4];
            ulonglong2 bh = *(const ulonglong2*)&Bs[kk][tx * 4 + 32];
            ull ap[8];
            ap[0] = pk2(a0.x); ap[1] = pk2(a0.y); ap[2] = pk2(a0.z); ap[3] = pk2(a0.w);
            ap[4] = pk2(a1.x); ap[5] = pk2(a1.y); ap[6] = pk2(a1.z); ap[7] = pk2(a1.w);
            #pragma unroll
            for (int i = 0; i < 8; ++i) {
                fma2(acc[i][0], ap[i], bl.x);
                fma2(acc[i][1], ap[i], bl.y);
                fma2(acc[i][2], ap[i], bh.x);
                fma2(acc[i][3], ap[i], bh.y);
            }
        }
        __syncthreads();
    }

    float alpha = 1.f;
    if (SCALE) alpha = *alpha_ptr;

    #pragma unroll
    for (int i = 0; i < 8; ++i) {
        int r = row0 + ty * 4 + (i & 3) + (i >> 2) * 32;
        #pragma unroll
        for (int half = 0; half < 2; ++half) {
            int c = col0 + tx * 4 + half * 32;
            float2 p0 = up2(acc[i][half * 2 + 0]);
            float2 p1 = up2(acc[i][half * 2 + 1]);
            float4 v = make_float4(p0.x, p0.y, p1.x, p1.y);
            if (BIAS) {
                float4 bv = *(const float4*)&bias[c];
                v.x += bv.x; v.y += bv.y; v.z += bv.z; v.w += bv.w;
            }
            if (RELU) {
                v.x = fmaxf(v.x, 0.f); v.y = fmaxf(v.y, 0.f);
                v.z = fmaxf(v.z, 0.f); v.w = fmaxf(v.w, 0.f);
            }
            v.x *= alpha; v.y *= alpha; v.z *= alpha; v.w *= alpha;
            *(float4*)&C[(long)r * ldc + c] = v;
        }
    }
}

// ---------------- fused pairwise logits + softmax (v2, FFMA2) ----------------
// One block (128 thr) per p-row. q-tile 128, microtile 8q x 12m, K=48 in 2 phases of 24.
__global__ __launch_bounds__(128)
void pairwise_kernel(const float* __restrict__ Zj, const float* __restrict__ Zi,
                     const float* __restrict__ tjb, const float* __restrict__ ti,
                     const float* __restrict__ Ws1, const float* __restrict__ ws2,
                     const float* __restrict__ bs2, const int* __restrict__ attn_mask,
                     float* __restrict__ probs)
{
    __shared__ float Wc_s[48][96];     // Ws1 rows 48..95  (18 KB)
    __shared__ float Gs[24][128];      // one K-phase of G (12 KB)
    __shared__ float Zis[128][25];     // q-tile of Zi     (12.5 KB)
    __shared__ float logits_s[512];
    __shared__ float Zjp_s[24];
    __shared__ float tjb_s[96];
    __shared__ float ws2_s[96];
    __shared__ float red_s[8];

    const int tid = threadIdx.x;
    const int tx = tid & 7;            // m-group (12 cols each)
    const int ty = tid >> 3;           // q-group (8 rows each), 0..15
    const int pg = blockIdx.x;         // 0..2047
    const int b = pg >> 9;

    for (int idx = tid; idx < 48 * 96; idx += 128)
        (&Wc_s[0][0])[idx] = Ws1[48 * 96 + idx];
    if (tid < 24) Zjp_s[tid] = Zj[pg * 24 + tid];
    if (tid < 96) { tjb_s[tid] = tjb[pg * 96 + tid]; ws2_s[tid] = ws2[tid]; }
    __syncthreads();

    #pragma unroll 1
    for (int qt = 0; qt < 4; ++qt) {
        const int q0 = qt * 128;
        // load Zi tile
        for (int idx = tid; idx < 128 * 24; idx += 128) {
            int q = idx / 24, d = idx - q * 24;
            Zis[q][d] = Zi[((long)(b * 512 + q0 + q)) * 24 + d];
        }
        __syncthreads();

        ull acc[8][6];
        #pragma unroll
        for (int i = 0; i < 8; ++i)
            #pragma unroll
            for (int j = 0; j < 6; ++j) acc[i][j] = 0ull;

        #pragma unroll 1
        for (int ph = 0; ph < 2; ++ph) {
            // build G phase: k 0..23 -> product (ph=0) or |diff| (ph=1)
            for (int idx = tid; idx < 24 * 128; idx += 128) {
                int k = idx >> 7, q = idx & 127;
                float zj = Zjp_s[k], zi = Zis[q][k];
                Gs[k][q] = ph ? fabsf(zj - zi) : zj * zi;
            }
            __syncthreads();
            const int kbase = ph * 24;
            #pragma unroll
            for (int k = 0; k < 24; ++k) {
                float4 g0 = *(const float4*)&Gs[k][ty * 8];
                float4 g1 = *(const float4*)&Gs[k][ty * 8 + 4];
                ulonglong2 w0 = *(const ulonglong2*)&Wc_s[kbase + k][tx * 12];
                ulonglong2 w1 = *(const ulonglong2*)&Wc_s[kbase + k][tx * 12 + 4];
                ulonglong2 w2 = *(const ulonglong2*)&Wc_s[kbase + k][tx * 12 + 8];
                ull gp[8];
                gp[0] = pk2(g0.x); gp[1] = pk2(g0.y); gp[2] = pk2(g0.z); gp[3] = pk2(g0.w);
                gp[4] = pk2(g1.x); gp[5] = pk2(g1.y); gp[6] = pk2(g1.z); gp[7] = pk2(g1.w);
                #pragma unroll
                for (int i = 0; i < 8; ++i) {
                    fma2(acc[i][0], gp[i], w0.x);
                    fma2(acc[i][1], gp[i], w0.y);
                    fma2(acc[i][2], gp[i], w1.x);
                    fma2(acc[i][3], gp[i], w1.y);
                    fma2(acc[i][4], gp[i], w2.x);
                    fma2(acc[i][5], gp[i], w2.y);
                }
            }
            __syncthreads();
        }

        // epilogue: + tjb + ti, relu, dot ws2, reduce over the 8 tx lanes
        #pragma unroll
        for (int i = 0; i < 8; ++i) {
            int q = ty * 8 + i;
            const float* tirow = &ti[((long)(b * 512 + q0 + q)) * 96 + tx * 12];
            float s = 0.f;
            #pragma unroll
            for (int j = 0; j < 6; ++j) {
                int m = tx * 12 + 2 * j;
                float2 a = up2(acc[i][j]);
                float2 t = *(const float2*)&tirow[2 * j];
                float h0 = fmaxf(a.x + tjb_s[m] + t.x, 0.f);
                float h1 = fmaxf(a.y + tjb_s[m + 1] + t.y, 0.f);
                s = fmaf(h0, ws2_s[m], s);
                s = fmaf(h1, ws2_s[m + 1], s);
            }
            s += __shfl_xor_sync(0xffffffffu, s, 1);
            s += __shfl_xor_sync(0xffffffffu, s, 2);
            s += __shfl_xor_sync(0xffffffffu, s, 4);
            if (tx == 0) logits_s[q0 + q] = s;
        }
    }
    __syncthreads();

    // mask + bs2
    const float bs2v = *bs2;
    #pragma unroll
    for (int q = tid; q < 512; q += 128) {
        float mv = (float)attn_mask[b * 512 + q];
        logits_s[q] += bs2v + (1.f - mv) * (-3.402823466e38f);
    }
    __syncthreads();

    // softmax over 512 (128 threads, warp shuffles + 4-warp combine)
    const int wid = tid >> 5, lane = tid & 31;
    float lmax = -INFINITY;
    #pragma unroll
    for (int q = tid; q < 512; q += 128) lmax = fmaxf(lmax, logits_s[q]);
    #pragma unroll
    for (int o = 16; o > 0; o >>= 1) lmax = fmaxf(lmax, __shfl_xor_sync(0xffffffffu, lmax, o));
    if (lane == 0) red_s[wid] = lmax;
    __syncthreads();
    lmax = fmaxf(fmaxf(red_s[0], red_s[1]), fmaxf(red_s[2], red_s[3]));

    float lsum = 0.f;
    float ev[4];
    #pragma unroll
    for (int u = 0; u < 4; ++u) {
        int q = tid + u * 128;
        ev[u] = expf(logits_s[q] - lmax);
        lsum += ev[u];
    }
    #pragma unroll
    for (int o = 16; o > 0; o >>= 1) lsum += __shfl_xor_sync(0xffffffffu, lsum, o);
    if (lane == 0) red_s[4 + wid] = lsum;
    __syncthreads();
    const float inv = 1.f / (red_s[4] + red_s[5] + red_s[6] + red_s[7]);
    #pragma unroll
    for (int u = 0; u < 4; ++u) {
        int q = tid + u * 128;
        probs[(long)pg * 512 + q] = ev[u] * inv;
    }
}

// ---------------- launch ----------------
extern "C" void kernel_launch(void* const* d_in, const int* in_sizes, int n_in,
                              void* d_out, int out_size)
{
    const float* Hj   = (const float*)d_in[0];
    const float* Hi   = (const float*)d_in[1];
    const float* Wpj  = (const float*)d_in[2];
    const float* Wpi  = (const float*)d_in[3];
    const float* Ws1  = (const float*)d_in[4];
    const float* bs1  = (const float*)d_in[5];
    const float* ws2  = (const float*)d_in[6];
    const float* bs2  = (const float*)d_in[7];
    const float* Wv1  = (const float*)d_in[8];
    const float* bv1  = (const float*)d_in[9];
    const float* Wv2  = (const float*)d_in[10];
    const float* bv2  = (const float*)d_in[11];
    const float* alpha= (const float*)d_in[12];
    const int*   mask = (const int*)d_in[13];
    float* out = (float*)d_out;

    float *Zj, *Zi, *tjb, *ti, *probs, *ctx, *mhid;
    cudaGetSymbolAddress((void**)&Zj, g_Zj);
    cudaGetSymbolAddress((void**)&Zi, g_Zi);
    cudaGetSymbolAddress((void**)&tjb, g_tjb);
    cudaGetSymbolAddress((void**)&ti, g_ti);
    cudaGetSymbolAddress((void**)&probs, g_probs);
    cudaGetSymbolAddress((void**)&ctx, g_ctx);
    cudaGetSymbolAddress((void**)&mhid, g_mhid);

    // Zj = H_j @ Wpj ; Zi = H_i @ Wpi          (2048 x 24, K=768)
    sgemm_small<false><<<dim3(1, ROWS/64, 1), 256>>>(
        Hj, Wpj, Zj, ROWS, DD, HD, HD, DD, DD, nullptr);
    sgemm_small<false><<<dim3(1, ROWS/64, 1), 256>>>(
        Hi, Wpi, Zi, ROWS, DD, HD, HD, DD, DD, nullptr);

    // tjb = Zj @ Ws1[0:24] + bs1 ; ti = Zi @ Ws1[24:48]   (2048 x 96, K=24)
    sgemm_small<true><<<dim3(2, ROWS/64, 1), 256>>>(
        Zj, Ws1, tjb, ROWS, MMDIM, DD, DD, MMDIM, MMDIM, bs1);
    sgemm_small<false><<<dim3(2, ROWS/64, 1), 256>>>(
        Zi, Ws1 + DD * MMDIM, ti, ROWS, MMDIM, DD, DD, MMDIM, MMDIM, nullptr);

    // fused pairwise logits + softmax -> probs
    pairwise_kernel<<<ROWS, 128>>>(Zj, Zi, tjb, ti, Ws1, ws2, bs2, mask, probs);

    // ctx = probs @ H_i   (batched 4x: 512 x 768, K=512)
    gemm64<0,false,false,false><<<dim3(HD/64, SEQ/64, BATCH), 64>>>(
        probs, Hi, ctx, SEQ, SEQ, HD, HD, nullptr, nullptr,
        (long)SEQ*SEQ, (long)SEQ*HD, (long)SEQ*HD, nullptr, nullptr);

    // mhid = relu([ctx|Hj|ctx*Hj] @ Wv1 + bv1)   (2048 x 768, K=2304; X fused)
    gemm64<1,true,true,false><<<dim3(OO/64, ROWS/64, 1), 64>>>(
        nullptr, Wv1, mhid, XCOLS, 0, OO, OO, bv1, nullptr,
        0, 0, 0, ctx, Hj);

    // out = alpha * (mhid @ Wv2 + bv2)   (2048 x 768, K=768)
    gemm64<0,true,false,true><<<dim3(HD/64, ROWS/64, 1), 64>>>(
        mhid, Wv2, out, OO, OO, HD, HD, bv2, alpha,
        0, 0, 0, nullptr, nullptr);
}

// round 3
// speedup vs baseline: 1.5199x; 1.2949x over previous
#include <cuda_runtime.h>
#include <math.h>

#define BATCH 4
#define SEQ   512
#define HD    768
#define DD    24
#define MMDIM 96
#define OO    768
#define ROWS  (BATCH*SEQ)       // 2048
#define XCOLS (3*HD)            // 2304

typedef unsigned long long ull;

// ---------------- scratch (no allocations allowed) ----------------
__device__ float g_Zj[ROWS*DD];
__device__ float g_Zi[ROWS*DD];
__device__ float g_tjb[ROWS*MMDIM];
__device__ float g_ti[ROWS*MMDIM];
__device__ float g_probs[(long)BATCH*SEQ*SEQ];
__device__ float g_ctx[(long)ROWS*HD];
__device__ float g_mhid[(long)ROWS*OO];

// ---------------- packed f32x2 helpers ----------------
__device__ __forceinline__ ull pk2(float x) {
    ull r; asm("mov.b64 %0, {%1, %1};" : "=l"(r) : "f"(x)); return r;
}
__device__ __forceinline__ void fma2(ull &d, ull a, ull b) {
    asm("fma.rn.f32x2 %0, %1, %2, %0;" : "+l"(d) : "l"(a), "l"(b));
}
__device__ __forceinline__ float2 up2(ull v) {
    float2 r; asm("mov.b64 {%0, %1}, %2;" : "=f"(r.x), "=f"(r.y) : "l"(v)); return r;
}

// ---------------- small generic SGEMM, z-batched over pointer pairs ----------------
__global__ __launch_bounds__(256)
void sgemm_small2(const float* __restrict__ A0, const float* __restrict__ B0,
                  float* __restrict__ C0, const float* __restrict__ bias0,
                  const float* __restrict__ A1, const float* __restrict__ B1,
                  float* __restrict__ C1, const float* __restrict__ bias1,
                  int M, int N, int K, int lda, int ldb, int ldc)
{
    __shared__ float As[16][64];
    __shared__ float Bs[16][64];
    const float* A = blockIdx.z ? A1 : A0;
    const float* B = blockIdx.z ? B1 : B0;
    float*       C = blockIdx.z ? C1 : C0;
    const float* bias = blockIdx.z ? bias1 : bias0;

    const int tid = threadIdx.x;
    const int tx = tid & 15, ty = tid >> 4;
    const int row0 = blockIdx.y * 64;
    const int col0 = blockIdx.x * 64;

    float acc[4][4] = {};
    for (int k0 = 0; k0 < K; k0 += 16) {
        #pragma unroll
        for (int u = 0; u < 4; ++u) {
            int t = tid + u * 256;
            int r = t >> 4, kk = t & 15;
            int gr = row0 + r, gk = k0 + kk;
            float v = 0.f;
            if (gr < M && gk < K) v = A[(long)gr * lda + gk];
            As[kk][r] = v;
        }
        #pragma unroll
        for (int u = 0; u < 4; ++u) {
            int t = tid + u * 256;
            int kk = t >> 6, n = t & 63;
            int gk = k0 + kk, gn = col0 + n;
            float v = 0.f;
            if (gk < K && gn < N) v = B[(long)gk * ldb + gn];
            Bs[kk][n] = v;
        }
        __syncthreads();
        #pragma unroll
        for (int kk = 0; kk < 16; ++kk) {
            float4 a4 = *(const float4*)&As[kk][ty * 4];
            float4 b4 = *(const float4*)&Bs[kk][tx * 4];
            float a[4] = {a4.x, a4.y, a4.z, a4.w};
            float b[4] = {b4.x, b4.y, b4.z, b4.w};
            #pragma unroll
            for (int i = 0; i < 4; ++i)
                #pragma unroll
                for (int j = 0; j < 4; ++j)
                    acc[i][j] = fmaf(a[i], b[j], acc[i][j]);
        }
        __syncthreads();
    }
    #pragma unroll
    for (int i = 0; i < 4; ++i) {
        int r = row0 + ty * 4 + i;
        if (r >= M) continue;
        #pragma unroll
        for (int j = 0; j < 4; ++j) {
            int c = col0 + tx * 4 + j;
            if (c >= N) continue;
            float v = acc[i][j];
            if (bias) v += bias[c];
            C[(long)r * ldc + c] = v;
        }
    }
}

// ---------------- 64x64 FFMA2 GEMM, KT=32, register-prefetch pipelined ----------------
// 128 threads; thread tile 8 rows x 4 cols. Exact-multiple dims, unguarded.
// AMODE 0: A pointer. AMODE 1: A = [ctx | Hj | ctx*Hj] generated on the fly.
template<int AMODE, bool BIAS, bool RELU, bool SCALE>
__global__ __launch_bounds__(128)
void gemm128(const float* __restrict__ A, const float* __restrict__ B,
             float* __restrict__ C, int K, int lda, int ldb, int ldc,
             const float* __restrict__ bias, const float* __restrict__ alpha_ptr,
             long sA, long sB, long sC,
             const float* __restrict__ Actx, const float* __restrict__ Ahj)
{
    __shared__ float As[32][68];
    __shared__ float Bs[32][68];

    const int bz = blockIdx.z;
    if (AMODE == 0) A += (long)bz * sA;
    B += (long)bz * sB;  C += (long)bz * sC;

    const int tid = threadIdx.x;
    const int tx = tid & 15, ty = tid >> 4;       // tx: col grp (4), ty: row grp (8)
    const int row0 = blockIdx.y * 64;
    const int col0 = blockIdx.x * 64;

    // per-thread load indices
    const int ar = tid >> 3, akc = tid & 7;       // A: rows ar + {0,16,32,48}? no: passes below
    const int bk = tid >> 4, bn4 = tid & 15;      // B: k rows bk + u*8

    ull acc[8][2];
    #pragma unroll
    for (int i = 0; i < 8; ++i) { acc[i][0] = 0ull; acc[i][1] = 0ull; }

    float4 pa[4], pb[4];

    // ---- prefetch helper (macro-ish via lambda) ----
    auto loadA = [&](int kt, float4* dst) {
        #pragma unroll
        for (int u = 0; u < 4; ++u) {
            int r = ar + u * 16;                  // 0..63
            int gk = kt + akc * 4;
            if (AMODE == 0) {
                dst[u] = *(const float4*)&A[(long)(row0 + r) * lda + gk];
            } else {
                long ridx = (long)(row0 + r) * HD;
                if (gk < HD) {
                    dst[u] = *(const float4*)&Actx[ridx + gk];
                } else if (gk < 2 * HD) {
                    dst[u] = *(const float4*)&Ahj[ridx + gk - HD];
                } else {
                    float4 c4 = *(const float4*)&Actx[ridx + gk - 2 * HD];
                    float4 h4 = *(const float4*)&Ahj[ridx + gk - 2 * HD];
                    dst[u].x = c4.x * h4.x; dst[u].y = c4.y * h4.y;
                    dst[u].z = c4.z * h4.z; dst[u].w = c4.w * h4.w;
                }
            }
        }
    };
    auto loadB = [&](int kt, float4* dst) {
        #pragma unroll
        for (int u = 0; u < 4; ++u)
            dst[u] = *(const float4*)&B[(long)(kt + bk + u * 8) * ldb + col0 + bn4 * 4];
    };
    auto storeTiles = [&](const float4* a, const float4* b) {
        #pragma unroll
        for (int u = 0; u < 4; ++u) {
            int r = ar + u * 16;
            As[akc * 4 + 0][r] = a[u].x;
            As[akc * 4 + 1][r] = a[u].y;
            As[akc * 4 + 2][r] = a[u].z;
            As[akc * 4 + 3][r] = a[u].w;
            *(float4*)&Bs[bk + u * 8][bn4 * 4] = b[u];
        }
    };

    loadA(0, pa); loadB(0, pb);
    storeTiles(pa, pb);
    __syncthreads();

    for (int kt = 0; kt < K; kt += 32) {
        const bool more = (kt + 32) < K;
        if (more) { loadA(kt + 32, pa); loadB(kt + 32, pb); }

        #pragma unroll
        for (int kk = 0; kk < 32; ++kk) {
            float4 a0 = *(const float4*)&As[kk][ty * 8];
            float4 a1 = *(const float4*)&As[kk][ty * 8 + 4];
            ulonglong2 bl = *(const ulonglong2*)&Bs[kk][tx * 4];
            ull ap[8];
            ap[0] = pk2(a0.x); ap[1] = pk2(a0.y); ap[2] = pk2(a0.z); ap[3] = pk2(a0.w);
            ap[4] = pk2(a1.x); ap[5] = pk2(a1.y); ap[6] = pk2(a1.z); ap[7] = pk2(a1.w);
            #pragma unroll
            for (int i = 0; i < 8; ++i) {
                fma2(acc[i][0], ap[i], bl.x);
                fma2(acc[i][1], ap[i], bl.y);
            }
        }
        __syncthreads();
        if (more) {
            storeTiles(pa, pb);
            __syncthreads();
        }
    }

    float alpha = 1.f;
    if (SCALE) alpha = *alpha_ptr;

    float4 bv;
    if (BIAS) bv = *(const float4*)&bias[col0 + tx * 4];

    #pragma unroll
    for (int i = 0; i < 8; ++i) {
        int r = row0 + ty * 8 + i;
        int c = col0 + tx * 4;
        float2 p0 = up2(acc[i][0]);
        float2 p1 = up2(acc[i][1]);
        float4 v = make_float4(p0.x, p0.y, p1.x, p1.y);
        if (BIAS) { v.x += bv.x; v.y += bv.y; v.z += bv.z; v.w += bv.w; }
        if (RELU) {
            v.x = fmaxf(v.x, 0.f); v.y = fmaxf(v.y, 0.f);
            v.z = fmaxf(v.z, 0.f); v.w = fmaxf(v.w, 0.f);
        }
        v.x *= alpha; v.y *= alpha; v.z *= alpha; v.w *= alpha;
        *(float4*)&C[(long)r * ldc + c] = v;
    }
}

// ---------------- fused pairwise logits + softmax (FFMA2) ----------------
// One block (128 thr) per p-row. q-tile 128, microtile 8q x 12m, K=48 in 2 phases of 24.
__global__ __launch_bounds__(128)
void pairwise_kernel(const float* __restrict__ Zj, const float* __restrict__ Zi,
                     const float* __restrict__ tjb, const float* __restrict__ ti,
                     const float* __restrict__ Ws1, const float* __restrict__ ws2,
                     const float* __restrict__ bs2, const int* __restrict__ attn_mask,
                     float* __restrict__ probs)
{
    __shared__ float Wc_s[48][96];
    __shared__ float Gs[24][128];
    __shared__ float Zis[128][25];
    __shared__ float logits_s[512];
    __shared__ float Zjp_s[24];
    __shared__ float tjb_s[96];
    __shared__ float ws2_s[96];
    __shared__ float red_s[8];

    const int tid = threadIdx.x;
    const int tx = tid & 7;
    const int ty = tid >> 3;
    const int pg = blockIdx.x;
    const int b = pg >> 9;

    for (int idx = tid; idx < 48 * 96; idx += 128)
        (&Wc_s[0][0])[idx] = Ws1[48 * 96 + idx];
    if (tid < 24) Zjp_s[tid] = Zj[pg * 24 + tid];
    if (tid < 96) { tjb_s[tid] = tjb[pg * 96 + tid]; ws2_s[tid] = ws2[tid]; }
    __syncthreads();

    #pragma unroll 1
    for (int qt = 0; qt < 4; ++qt) {
        const int q0 = qt * 128;
        for (int idx = tid; idx < 128 * 24; idx += 128) {
            int q = idx / 24, d = idx - q * 24;
            Zis[q][d] = Zi[((long)(b * 512 + q0 + q)) * 24 + d];
        }
        __syncthreads();

        ull acc[8][6];
        #pragma unroll
        for (int i = 0; i < 8; ++i)
            #pragma unroll
            for (int j = 0; j < 6; ++j) acc[i][j] = 0ull;

        #pragma unroll 1
        for (int ph = 0; ph < 2; ++ph) {
            for (int idx = tid; idx < 24 * 128; idx += 128) {
                int k = idx >> 7, q = idx & 127;
                float zj = Zjp_s[k], zi = Zis[q][k];
                Gs[k][q] = ph ? fabsf(zj - zi) : zj * zi;
            }
            __syncthreads();
            const int kbase = ph * 24;
            #pragma unroll
            for (int k = 0; k < 24; ++k) {
                float4 g0 = *(const float4*)&Gs[k][ty * 8];
                float4 g1 = *(const float4*)&Gs[k][ty * 8 + 4];
                ulonglong2 w0 = *(const ulonglong2*)&Wc_s[kbase + k][tx * 12];
                ulonglong2 w1 = *(const ulonglong2*)&Wc_s[kbase + k][tx * 12 + 4];
                ulonglong2 w2 = *(const ulonglong2*)&Wc_s[kbase + k][tx * 12 + 8];
                ull gp[8];
                gp[0] = pk2(g0.x); gp[1] = pk2(g0.y); gp[2] = pk2(g0.z); gp[3] = pk2(g0.w);
                gp[4] = pk2(g1.x); gp[5] = pk2(g1.y); gp[6] = pk2(g1.z); gp[7] = pk2(g1.w);
                #pragma unroll
                for (int i = 0; i < 8; ++i) {
                    fma2(acc[i][0], gp[i], w0.x);
                    fma2(acc[i][1], gp[i], w0.y);
                    fma2(acc[i][2], gp[i], w1.x);
                    fma2(acc[i][3], gp[i], w1.y);
                    fma2(acc[i][4], gp[i], w2.x);
                    fma2(acc[i][5], gp[i], w2.y);
                }
            }
            __syncthreads();
        }

        #pragma unroll
        for (int i = 0; i < 8; ++i) {
            int q = ty * 8 + i;
            const float* tirow = &ti[((long)(b * 512 + q0 + q)) * 96 + tx * 12];
            float s = 0.f;
            #pragma unroll
            for (int j = 0; j < 6; ++j) {
                int m = tx * 12 + 2 * j;
                float2 a = up2(acc[i][j]);
                float2 t = *(const float2*)&tirow[2 * j];
                float h0 = fmaxf(a.x + tjb_s[m] + t.x, 0.f);
                float h1 = fmaxf(a.y + tjb_s[m + 1] + t.y, 0.f);
                s = fmaf(h0, ws2_s[m], s);
                s = fmaf(h1, ws2_s[m + 1], s);
            }
            s += __shfl_xor_sync(0xffffffffu, s, 1);
            s += __shfl_xor_sync(0xffffffffu, s, 2);
            s += __shfl_xor_sync(0xffffffffu, s, 4);
            if (tx == 0) logits_s[q0 + q] = s;
        }
    }
    __syncthreads();

    const float bs2v = *bs2;
    #pragma unroll
    for (int q = tid; q < 512; q += 128) {
        float mv = (float)attn_mask[b * 512 + q];
        logits_s[q] += bs2v + (1.f - mv) * (-3.402823466e38f);
    }
    __syncthreads();

    const int wid = tid >> 5, lane = tid & 31;
    float lmax = -INFINITY;
    #pragma unroll
    for (int q = tid; q < 512; q += 128) lmax = fmaxf(lmax, logits_s[q]);
    #pragma unroll
    for (int o = 16; o > 0; o >>= 1) lmax = fmaxf(lmax, __shfl_xor_sync(0xffffffffu, lmax, o));
    if (lane == 0) red_s[wid] = lmax;
    __syncthreads();
    lmax = fmaxf(fmaxf(red_s[0], red_s[1]), fmaxf(red_s[2], red_s[3]));

    float lsum = 0.f;
    float ev[4];
    #pragma unroll
    for (int u = 0; u < 4; ++u) {
        int q = tid + u * 128;
        ev[u] = expf(logits_s[q] - lmax);
        lsum += ev[u];
    }
    #pragma unroll
    for (int o = 16; o > 0; o >>= 1) lsum += __shfl_xor_sync(0xffffffffu, lsum, o);
    if (lane == 0) red_s[4 + wid] = lsum;
    __syncthreads();
    const float inv = 1.f / (red_s[4] + red_s[5] + red_s[6] + red_s[7]);
    #pragma unroll
    for (int u = 0; u < 4; ++u) {
        int q = tid + u * 128;
        probs[(long)pg * 512 + q] = ev[u] * inv;
    }
}

// ---------------- launch ----------------
extern "C" void kernel_launch(void* const* d_in, const int* in_sizes, int n_in,
                              void* d_out, int out_size)
{
    const float* Hj   = (const float*)d_in[0];
    const float* Hi   = (const float*)d_in[1];
    const float* Wpj  = (const float*)d_in[2];
    const float* Wpi  = (const float*)d_in[3];
    const float* Ws1  = (const float*)d_in[4];
    const float* bs1  = (const float*)d_in[5];
    const float* ws2  = (const float*)d_in[6];
    const float* bs2  = (const float*)d_in[7];
    const float* Wv1  = (const float*)d_in[8];
    const float* bv1  = (const float*)d_in[9];
    const float* Wv2  = (const float*)d_in[10];
    const float* bv2  = (const float*)d_in[11];
    const float* alpha= (const float*)d_in[12];
    const int*   mask = (const int*)d_in[13];
    float* out = (float*)d_out;

    float *Zj, *Zi, *tjb, *ti, *probs, *ctx, *mhid;
    cudaGetSymbolAddress((void**)&Zj, g_Zj);
    cudaGetSymbolAddress((void**)&Zi, g_Zi);
    cudaGetSymbolAddress((void**)&tjb, g_tjb);
    cudaGetSymbolAddress((void**)&ti, g_ti);
    cudaGetSymbolAddress((void**)&probs, g_probs);
    cudaGetSymbolAddress((void**)&ctx, g_ctx);
    cudaGetSymbolAddress((void**)&mhid, g_mhid);

    // Zj = H_j @ Wpj ; Zi = H_i @ Wpi   (2048 x 24, K=768), batched
    sgemm_small2<<<dim3(1, ROWS/64, 2), 256>>>(
        Hj, Wpj, Zj, nullptr, Hi, Wpi, Zi, nullptr,
        ROWS, DD, HD, HD, DD, DD);

    // tjb = Zj @ Ws1[0:24] + bs1 ; ti = Zi @ Ws1[24:48]   (2048 x 96, K=24), batched
    sgemm_small2<<<dim3(2, ROWS/64, 2), 256>>>(
        Zj, Ws1, tjb, bs1, Zi, Ws1 + DD * MMDIM, ti, nullptr,
        ROWS, MMDIM, DD, DD, MMDIM, MMDIM);

    // fused pairwise logits + softmax -> probs
    pairwise_kernel<<<ROWS, 128>>>(Zj, Zi, tjb, ti, Ws1, ws2, bs2, mask, probs);

    // ctx = probs @ H_i   (batched 4x: 512 x 768, K=512)
    gemm128<0,false,false,false><<<dim3(HD/64, SEQ/64, BATCH), 128>>>(
        probs, Hi, ctx, SEQ, SEQ, HD, HD, nullptr, nullptr,
        (long)SEQ*SEQ, (long)SEQ*HD, (long)SEQ*HD, nullptr, nullptr);

    // mhid = relu([ctx|Hj|ctx*Hj] @ Wv1 + bv1)   (2048 x 768, K=2304; X fused)
    gemm128<1,true,true,false><<<dim3(OO/64, ROWS/64, 1), 128>>>(
        nullptr, Wv1, mhid, XCOLS, 0, OO, OO, bv1, nullptr,
        0, 0, 0, ctx, Hj);

    // out = alpha * (mhid @ Wv2 + bv2)   (2048 x 768, K=768)
    gemm128<0,true,false,true><<<dim3(HD/64, ROWS/64, 1), 128>>>(
        mhid, Wv2, out, OO, OO, HD, HD, bv2, alpha,
        0, 0, 0, nullptr, nullptr);
}